// round 3
// baseline (speedup 1.0000x reference)
#include <cuda_runtime.h>
#include <cuda_bf16.h>
#include <cstdint>

// ---------------------------------------------------------------------------
// BlockDiagonalGRU via mma.sync tf32 + cp.async + ldmatrix (sm_100 base).
//   x:(1024,4096) h:(1024,4096) W_ih:(8,1536,512) W_hh:(8,1536,512)
//   b_ih:(8,1536) b_hh:(8,1536) -> out:(1024,4096), fp32
//
// Grid: 512 CTAs = nb(8) x ctile(8 x 64 cols) x mtile(8 x 128 rows), m fastest.
// CTA tile 128x64 per gate; 8 warps as 4(m) x 2(n), warp tile 32x32.
// Accs: R (i_r+h_r fused), Z (fused), IN, HN -> 128 f32/thread.
// 4-stage cp.async pipeline, TK=32. A frags cvt.rna to tf32; W frags fed as
// raw fp32 (HW RZ-truncation) compensated by x(1+2^-11) in the epilogue.
// ---------------------------------------------------------------------------

namespace {

constexpr int HID = 4096;
constexpr int BS  = 512;
constexpr int G3  = 1536;

constexpr int STRIDE = 36;                      // words per 32-k row (+4 pad)
constexpr int A_ROWS = 128;
constexpr int B_ROWS = 192;                     // 3 gates x 64
constexpr int A_FB    = A_ROWS * STRIDE * 4;    // 18432 B
constexpr int STAGE_B = (A_ROWS + B_ROWS) * STRIDE * 4;  // 46080 B
constexpr int STAGES  = 4;
constexpr int SMEM_BYTES = STAGES * STAGE_B;    // 184320 B

constexpr float COMP = 1.00048828125f;          // 1 + 2^-11: W truncation bias fix

__device__ __forceinline__ uint32_t smem_u32(const void* p) {
    uint32_t a;
    asm("{ .reg .u64 t; cvta.to.shared.u64 t, %1; cvt.u32.u64 %0, t; }"
        : "=r"(a) : "l"(p));
    return a;
}
__device__ __forceinline__ uint32_t f2tf32(uint32_t f) {
    uint32_t r;
    asm("cvt.rna.tf32.f32 %0, %1;" : "=r"(r) : "r"(f));
    return r;
}
__device__ __forceinline__ float tanh_ap(float x) {
    float y;
    asm("tanh.approx.f32 %0, %1;" : "=f"(y) : "f"(x));
    return y;
}
__device__ __forceinline__ float sig_ap(float x) {
    return fmaf(0.5f, tanh_ap(0.5f * x), 0.5f);
}
__device__ __forceinline__ void cp16(uint32_t dst, const void* src) {
    asm volatile("cp.async.cg.shared.global [%0], [%1], 16;"
                 :: "r"(dst), "l"(src) : "memory");
}
__device__ __forceinline__ void ldsm4(uint32_t* r, uint32_t addr) {
    asm volatile("ldmatrix.sync.aligned.m8n8.x4.shared.b16 {%0,%1,%2,%3}, [%4];"
                 : "=r"(r[0]), "=r"(r[1]), "=r"(r[2]), "=r"(r[3]) : "r"(addr));
}
__device__ __forceinline__ void mma8(float* c, const uint32_t* a, const uint32_t* b) {
    asm volatile(
        "mma.sync.aligned.m16n8k8.row.col.f32.tf32.tf32.f32 "
        "{%0,%1,%2,%3}, {%4,%5,%6,%7}, {%8,%9}, {%0,%1,%2,%3};"
        : "+f"(c[0]), "+f"(c[1]), "+f"(c[2]), "+f"(c[3])
        : "r"(a[0]), "r"(a[1]), "r"(a[2]), "r"(a[3]), "r"(b[0]), "r"(b[1]));
}

}  // namespace

__global__ __launch_bounds__(256, 1)
void BlockDiagonalGRU_kernel(
    const float* __restrict__ x, const float* __restrict__ h,
    const float* __restrict__ Wih, const float* __restrict__ Whh,
    const float* __restrict__ bih, const float* __restrict__ bhh,
    float* __restrict__ out)
{
    extern __shared__ float smf[];
    const uint32_t smb = smem_u32(smf);

    const int tid  = threadIdx.x;
    const int wid  = tid >> 5;
    const int lane = tid & 31;
    const int gq   = lane >> 2;
    const int t4   = lane & 3;

    const int m  = blockIdx.x & 7;
    const int c  = (blockIdx.x >> 3) & 7;
    const int nb = blockIdx.x >> 6;

    const int wr = (wid >> 1) * 32;
    const int wc = (wid & 1) * 32;

    // ---- fill assignments: 4 A-chunks + 6 W-chunks of 16B per thread ----
    int aoff[4];  uint32_t soffA[4];
    #pragma unroll
    for (int ii = 0; ii < 4; ++ii) {
        const int id = tid + 256 * ii;
        const int row = id >> 3, q = id & 7;
        aoff[ii]  = row * HID + q * 4;
        soffA[ii] = (uint32_t)(row * STRIDE * 4 + q * 16);
    }
    int woff[6];  uint32_t soffB[6];
    #pragma unroll
    for (int ii = 0; ii < 6; ++ii) {
        const int id = tid + 256 * ii;
        const int wrow = id >> 3, q = id & 7;
        const int gate = wrow >> 6, nl = wrow & 63;
        woff[ii]  = (gate * BS + c * 64 + nl) * BS + q * 4;
        soffB[ii] = (uint32_t)(A_FB + wrow * STRIDE * 4 + q * 16);
    }

    const float* Abase[2] = { x + (size_t)(m * 128) * HID + nb * BS,
                              h + (size_t)(m * 128) * HID + nb * BS };
    const float* Wbase[2] = { Wih + (size_t)nb * G3 * BS,
                              Whh + (size_t)nb * G3 * BS };

    // per-lane ldmatrix byte offsets
    const uint32_t laneA =
        (uint32_t)(((((lane >> 3) & 1) * 8 + (lane & 7)) * STRIDE + (lane >> 4) * 4) * 4);
    const uint32_t laneB =
        (uint32_t)((((lane >> 4) * 8 + (lane & 7)) * STRIDE + ((lane >> 3) & 1) * 4) * 4)
        + (uint32_t)A_FB;

    float accR[2][4][4] = {}, accZ[2][4][4] = {};
    float accI[2][4][4] = {}, accH[2][4][4] = {};

    auto fill = [&](int st, int it) {
        const int p  = it >> 4;
        const int kc = (it & 15) * 32;
        const uint32_t sb0 = smb + (uint32_t)(st * STAGE_B);
        const float* Ab = Abase[p] + kc;
        #pragma unroll
        for (int ii = 0; ii < 4; ++ii) cp16(sb0 + soffA[ii], Ab + aoff[ii]);
        const float* Wb = Wbase[p] + kc;
        #pragma unroll
        for (int ii = 0; ii < 6; ++ii) cp16(sb0 + soffB[ii], Wb + woff[ii]);
        asm volatile("cp.async.commit_group;" ::: "memory");
    };

    fill(0, 0); fill(1, 1); fill(2, 2);

    for (int i = 0; i < 32; ++i) {
        if (i <= 29)      asm volatile("cp.async.wait_group 2;" ::: "memory");
        else if (i == 30) asm volatile("cp.async.wait_group 1;" ::: "memory");
        else              asm volatile("cp.async.wait_group 0;" ::: "memory");
        __syncthreads();

        if (i < 29) fill((i + 3) & 3, i + 3);

        const uint32_t sA = smb + (uint32_t)((i & 3) * STAGE_B);
        float (*accN)[4][4] = (i >> 4) ? accH : accI;

        #pragma unroll
        for (int ks = 0; ks < 4; ++ks) {
            uint32_t a[2][4];
            #pragma unroll
            for (int mf = 0; mf < 2; ++mf) {
                ldsm4(a[mf], sA + laneA +
                      (uint32_t)(((wr + mf * 16) * STRIDE + ks * 8) * 4));
                #pragma unroll
                for (int j = 0; j < 4; ++j) a[mf][j] = f2tf32(a[mf][j]);
            }
            #pragma unroll
            for (int g = 0; g < 3; ++g) {
                #pragma unroll
                for (int pp = 0; pp < 2; ++pp) {
                    uint32_t b4[4];
                    ldsm4(b4, sA + laneB +
                          (uint32_t)(((wc + g * 64 + pp * 16) * STRIDE + ks * 8) * 4));
                    #pragma unroll
                    for (int n2 = 0; n2 < 2; ++n2) {
                        const int nf = pp * 2 + n2;
                        if (g == 0) {
                            mma8(accR[0][nf], a[0], b4 + n2 * 2);
                            mma8(accR[1][nf], a[1], b4 + n2 * 2);
                        } else if (g == 1) {
                            mma8(accZ[0][nf], a[0], b4 + n2 * 2);
                            mma8(accZ[1][nf], a[1], b4 + n2 * 2);
                        } else {
                            mma8(accN[0][nf], a[0], b4 + n2 * 2);
                            mma8(accN[1][nf], a[1], b4 + n2 * 2);
                        }
                    }
                }
            }
        }
    }

    // ---- fused GRU epilogue ----
    const float* bi = bih + nb * G3;
    const float* bh = bhh + nb * G3;

    #pragma unroll
    for (int mf = 0; mf < 2; ++mf) {
        #pragma unroll
        for (int nf = 0; nf < 4; ++nf) {
            const int colb = c * 64 + wc + nf * 8 + 2 * t4;
            const int rowb = m * 128 + wr + mf * 16 + gq;
            #pragma unroll
            for (int half = 0; half < 2; ++half) {
                const int row = rowb + 8 * half;
                const int i0  = 2 * half;
                const size_t goff = (size_t)row * HID + nb * BS + colb;
                const float2 hv = *reinterpret_cast<const float2*>(h + goff);
                float res[2];
                #pragma unroll
                for (int k = 0; k < 2; ++k) {
                    const int cb = colb + k;
                    const float rp = accR[mf][nf][i0 + k] * COMP
                                   + __ldg(bi + cb) + __ldg(bh + cb);
                    const float zp = accZ[mf][nf][i0 + k] * COMP
                                   + __ldg(bi + BS + cb) + __ldg(bh + BS + cb);
                    const float ip = accI[mf][nf][i0 + k] * COMP + __ldg(bi + 2 * BS + cb);
                    const float hp = accH[mf][nf][i0 + k] * COMP + __ldg(bh + 2 * BS + cb);
                    const float r  = sig_ap(rp);
                    const float z  = sig_ap(zp);
                    const float ng = tanh_ap(fmaf(r, hp, ip));
                    const float hval = (k == 0) ? hv.x : hv.y;
                    res[k] = fmaf(z, hval - ng, ng);
                }
                *reinterpret_cast<float2*>(out + goff) = make_float2(res[0], res[1]);
            }
        }
    }
}

extern "C" void kernel_launch(void* const* d_in, const int* in_sizes, int n_in,
                              void* d_out, int out_size) {
    (void)in_sizes; (void)n_in; (void)out_size;
    cudaFuncSetAttribute(BlockDiagonalGRU_kernel,
                         cudaFuncAttributeMaxDynamicSharedMemorySize, SMEM_BYTES);
    BlockDiagonalGRU_kernel<<<512, 256, SMEM_BYTES>>>(
        (const float*)d_in[0], (const float*)d_in[1],
        (const float*)d_in[2], (const float*)d_in[3],
        (const float*)d_in[4], (const float*)d_in[5],
        (float*)d_out);
}

// round 4
// speedup vs baseline: 1.0332x; 1.0332x over previous
#include <cuda_runtime.h>
#include <cuda_bf16.h>
#include <cstdint>

// ---------------------------------------------------------------------------
// BlockDiagonalGRU via mma.sync tf32 + cp.async + ldmatrix (sm_100 base).
// R4: 512 threads (16 warps, 4 per SMSP) to fix scheduler starvation.
//   Grid: 512 CTAs = nb(8) x ctile(8 x 64 cols) x mtile(8 x 128 rows).
//   CTA tile 128x64 per gate; warps 4(m) x 4(n), warp tile 32m x 16n.
//   Accs: R (i_r+h_r fused), Z (fused), IN, HN -> 64 f32/thread.
//   4-stage cp.async ring, TK=32. A frags cvt.rna->tf32; W raw fp32
//   (HW RZ truncation) compensated by x(1+2^-11) in the epilogue.
// ---------------------------------------------------------------------------

namespace {

constexpr int HID = 4096;
constexpr int BS  = 512;
constexpr int G3  = 1536;

constexpr int STRIDE = 36;                      // words per 32-k row (+4 pad)
constexpr int A_ROWS = 128;
constexpr int B_ROWS = 192;                     // 3 gates x 64
constexpr int A_FB    = A_ROWS * STRIDE * 4;    // 18432 B
constexpr int STAGE_B = (A_ROWS + B_ROWS) * STRIDE * 4;  // 46080 B
constexpr int STAGES  = 4;
constexpr int SMEM_BYTES = STAGES * STAGE_B;    // 184320 B

constexpr float COMP = 1.00048828125f;          // 1 + 2^-11

__device__ __forceinline__ uint32_t smem_u32(const void* p) {
    uint32_t a;
    asm("{ .reg .u64 t; cvta.to.shared.u64 t, %1; cvt.u32.u64 %0, t; }"
        : "=r"(a) : "l"(p));
    return a;
}
__device__ __forceinline__ uint32_t f2tf32(uint32_t f) {
    uint32_t r;
    asm("cvt.rna.tf32.f32 %0, %1;" : "=r"(r) : "r"(f));
    return r;
}
__device__ __forceinline__ float tanh_ap(float x) {
    float y;
    asm("tanh.approx.f32 %0, %1;" : "=f"(y) : "f"(x));
    return y;
}
__device__ __forceinline__ float sig_ap(float x) {
    return fmaf(0.5f, tanh_ap(0.5f * x), 0.5f);
}
__device__ __forceinline__ void cp16(uint32_t dst, const void* src) {
    asm volatile("cp.async.cg.shared.global [%0], [%1], 16;"
                 :: "r"(dst), "l"(src) : "memory");
}
__device__ __forceinline__ void ldsm4(uint32_t* r, uint32_t addr) {
    asm volatile("ldmatrix.sync.aligned.m8n8.x4.shared.b16 {%0,%1,%2,%3}, [%4];"
                 : "=r"(r[0]), "=r"(r[1]), "=r"(r[2]), "=r"(r[3]) : "r"(addr));
}
__device__ __forceinline__ void mma8(float* c, const uint32_t* a, const uint32_t* b) {
    asm volatile(
        "mma.sync.aligned.m16n8k8.row.col.f32.tf32.tf32.f32 "
        "{%0,%1,%2,%3}, {%4,%5,%6,%7}, {%8,%9}, {%0,%1,%2,%3};"
        : "+f"(c[0]), "+f"(c[1]), "+f"(c[2]), "+f"(c[3])
        : "r"(a[0]), "r"(a[1]), "r"(a[2]), "r"(a[3]), "r"(b[0]), "r"(b[1]));
}

}  // namespace

__global__ __launch_bounds__(512, 1)
void BlockDiagonalGRU_kernel(
    const float* __restrict__ x, const float* __restrict__ h,
    const float* __restrict__ Wih, const float* __restrict__ Whh,
    const float* __restrict__ bih, const float* __restrict__ bhh,
    float* __restrict__ out)
{
    extern __shared__ float smf[];
    const uint32_t smb = smem_u32(smf);

    const int tid  = threadIdx.x;
    const int wid  = tid >> 5;
    const int lane = tid & 31;
    const int gq   = lane >> 2;
    const int t4   = lane & 3;

    const int m  = blockIdx.x & 7;
    const int c  = (blockIdx.x >> 3) & 7;
    const int nb = blockIdx.x >> 6;

    const int wr = (wid >> 2) * 32;   // 4 m-groups of 32 rows
    const int wc = (wid & 3) * 16;    // 4 n-groups of 16 cols

    // ---- fill assignments: 2 A-chunks + 3 W-chunks of 16B per thread ----
    int aoff[2];  uint32_t soffA[2];
    #pragma unroll
    for (int ii = 0; ii < 2; ++ii) {
        const int id = tid + 512 * ii;
        const int row = id >> 3, q = id & 7;
        aoff[ii]  = row * HID + q * 4;
        soffA[ii] = (uint32_t)(row * STRIDE * 4 + q * 16);
    }
    int woff[3];  uint32_t soffB[3];
    #pragma unroll
    for (int ii = 0; ii < 3; ++ii) {
        const int id = tid + 512 * ii;
        const int wrow = id >> 3, q = id & 7;
        const int gate = wrow >> 6, nl = wrow & 63;
        woff[ii]  = (gate * BS + c * 64 + nl) * BS + q * 4;
        soffB[ii] = (uint32_t)(A_FB + wrow * STRIDE * 4 + q * 16);
    }

    const float* Abase[2] = { x + (size_t)(m * 128) * HID + nb * BS,
                              h + (size_t)(m * 128) * HID + nb * BS };
    const float* Wbase[2] = { Wih + (size_t)nb * G3 * BS,
                              Whh + (size_t)nb * G3 * BS };

    // per-lane ldmatrix byte offsets (validated layout from R3)
    const uint32_t laneA =
        (uint32_t)(((((lane >> 3) & 1) * 8 + (lane & 7)) * STRIDE + (lane >> 4) * 4) * 4);
    const uint32_t laneB =
        (uint32_t)((((lane >> 4) * 8 + (lane & 7)) * STRIDE + ((lane >> 3) & 1) * 4) * 4)
        + (uint32_t)A_FB;

    float accR[2][2][4] = {}, accZ[2][2][4] = {};
    float accI[2][2][4] = {}, accH[2][2][4] = {};

    auto fill = [&](int st, int it) {
        const int p  = it >> 4;
        const int kc = (it & 15) * 32;
        const uint32_t sb0 = smb + (uint32_t)(st * STAGE_B);
        const float* Ab = Abase[p] + kc;
        #pragma unroll
        for (int ii = 0; ii < 2; ++ii) cp16(sb0 + soffA[ii], Ab + aoff[ii]);
        const float* Wb = Wbase[p] + kc;
        #pragma unroll
        for (int ii = 0; ii < 3; ++ii) cp16(sb0 + soffB[ii], Wb + woff[ii]);
        asm volatile("cp.async.commit_group;" ::: "memory");
    };

    fill(0, 0); fill(1, 1); fill(2, 2);

    for (int i = 0; i < 32; ++i) {
        if (i <= 29)      asm volatile("cp.async.wait_group 2;" ::: "memory");
        else if (i == 30) asm volatile("cp.async.wait_group 1;" ::: "memory");
        else              asm volatile("cp.async.wait_group 0;" ::: "memory");
        __syncthreads();

        if (i < 29) fill((i + 3) & 3, i + 3);

        const uint32_t sA = smb + (uint32_t)((i & 3) * STAGE_B);
        float (*accN)[2][4] = (i >> 4) ? accH : accI;

        #pragma unroll
        for (int ks = 0; ks < 4; ++ks) {
            uint32_t a[2][4];
            #pragma unroll
            for (int mf = 0; mf < 2; ++mf) {
                ldsm4(a[mf], sA + laneA +
                      (uint32_t)(((wr + mf * 16) * STRIDE + ks * 8) * 4));
                #pragma unroll
                for (int j = 0; j < 4; ++j) a[mf][j] = f2tf32(a[mf][j]);
            }
            #pragma unroll
            for (int g = 0; g < 3; ++g) {
                uint32_t b4[4];
                ldsm4(b4, sA + laneB +
                      (uint32_t)(((wc + g * 64) * STRIDE + ks * 8) * 4));
                #pragma unroll
                for (int n2 = 0; n2 < 2; ++n2) {
                    if (g == 0) {
                        mma8(accR[0][n2], a[0], b4 + n2 * 2);
                        mma8(accR[1][n2], a[1], b4 + n2 * 2);
                    } else if (g == 1) {
                        mma8(accZ[0][n2], a[0], b4 + n2 * 2);
                        mma8(accZ[1][n2], a[1], b4 + n2 * 2);
                    } else {
                        mma8(accN[0][n2], a[0], b4 + n2 * 2);
                        mma8(accN[1][n2], a[1], b4 + n2 * 2);
                    }
                }
            }
        }
    }

    // ---- fused GRU epilogue ----
    const float* bi = bih + nb * G3;
    const float* bh = bhh + nb * G3;

    #pragma unroll
    for (int mf = 0; mf < 2; ++mf) {
        #pragma unroll
        for (int nf = 0; nf < 2; ++nf) {
            const int colb = c * 64 + wc + nf * 8 + 2 * t4;
            const int rowb = m * 128 + wr + mf * 16 + gq;
            #pragma unroll
            for (int half = 0; half < 2; ++half) {
                const int row = rowb + 8 * half;
                const int i0  = 2 * half;
                const size_t goff = (size_t)row * HID + nb * BS + colb;
                const float2 hv = *reinterpret_cast<const float2*>(h + goff);
                float res[2];
                #pragma unroll
                for (int k = 0; k < 2; ++k) {
                    const int cb = colb + k;
                    const float rp = accR[mf][nf][i0 + k] * COMP
                                   + __ldg(bi + cb) + __ldg(bh + cb);
                    const float zp = accZ[mf][nf][i0 + k] * COMP
                                   + __ldg(bi + BS + cb) + __ldg(bh + BS + cb);
                    const float ip = accI[mf][nf][i0 + k] * COMP + __ldg(bi + 2 * BS + cb);
                    const float hp = accH[mf][nf][i0 + k] * COMP + __ldg(bh + 2 * BS + cb);
                    const float r  = sig_ap(rp);
                    const float z  = sig_ap(zp);
                    const float ng = tanh_ap(fmaf(r, hp, ip));
                    const float hval = (k == 0) ? hv.x : hv.y;
                    res[k] = fmaf(z, hval - ng, ng);
                }
                *reinterpret_cast<float2*>(out + goff) = make_float2(res[0], res[1]);
            }
        }
    }
}

extern "C" void kernel_launch(void* const* d_in, const int* in_sizes, int n_in,
                              void* d_out, int out_size) {
    (void)in_sizes; (void)n_in; (void)out_size;
    cudaFuncSetAttribute(BlockDiagonalGRU_kernel,
                         cudaFuncAttributeMaxDynamicSharedMemorySize, SMEM_BYTES);
    BlockDiagonalGRU_kernel<<<512, 512, SMEM_BYTES>>>(
        (const float*)d_in[0], (const float*)d_in[1],
        (const float*)d_in[2], (const float*)d_in[3],
        (const float*)d_in[4], (const float*)d_in[5],
        (float*)d_out);
}

// round 5
// speedup vs baseline: 1.2028x; 1.1642x over previous
#include <cuda_runtime.h>
#include <cuda_bf16.h>
#include <cstdint>

// ---------------------------------------------------------------------------
// BlockDiagonalGRU via mma.sync tf32 + cp.async + ldmatrix (sm_100 base).
// R5: 2 CTAs/SM for cross-CTA overlap (fix barrier serialization).
//   Grid: 1024 CTAs = nb(8) x ctile(16 x 32 cols) x mtile(8 x 128 rows).
//   CTA tile 128x32 per gate; 256 thr, 8 warps as 4(m) x 2(n), warp 32x16.
//   Accs: R (i_r+h_r fused), Z (fused), IN, HN -> 64 f32/thread.
//   3-stage cp.async ring, TK=32. A frags cvt.rna->tf32; W raw fp32
//   (HW RZ truncation) compensated by x(1+2^-11) in the epilogue.
// ---------------------------------------------------------------------------

namespace {

constexpr int HID = 4096;
constexpr int BS  = 512;
constexpr int G3  = 1536;

constexpr int STRIDE = 36;                      // words per 32-k row (+4 pad)
constexpr int A_ROWS = 128;
constexpr int B_ROWS = 96;                      // 3 gates x 32
constexpr int A_FB    = A_ROWS * STRIDE * 4;    // 18432 B
constexpr int STAGE_B = (A_ROWS + B_ROWS) * STRIDE * 4;  // 32256 B
constexpr int STAGES  = 3;
constexpr int SMEM_BYTES = STAGES * STAGE_B;    // 96768 B

constexpr float COMP = 1.00048828125f;          // 1 + 2^-11

__device__ __forceinline__ uint32_t smem_u32(const void* p) {
    uint32_t a;
    asm("{ .reg .u64 t; cvta.to.shared.u64 t, %1; cvt.u32.u64 %0, t; }"
        : "=r"(a) : "l"(p));
    return a;
}
__device__ __forceinline__ uint32_t f2tf32(uint32_t f) {
    uint32_t r;
    asm("cvt.rna.tf32.f32 %0, %1;" : "=r"(r) : "r"(f));
    return r;
}
__device__ __forceinline__ float tanh_ap(float x) {
    float y;
    asm("tanh.approx.f32 %0, %1;" : "=f"(y) : "f"(x));
    return y;
}
__device__ __forceinline__ float sig_ap(float x) {
    return fmaf(0.5f, tanh_ap(0.5f * x), 0.5f);
}
__device__ __forceinline__ void cp16(uint32_t dst, const void* src) {
    asm volatile("cp.async.cg.shared.global [%0], [%1], 16;"
                 :: "r"(dst), "l"(src) : "memory");
}
__device__ __forceinline__ void ldsm4(uint32_t* r, uint32_t addr) {
    asm volatile("ldmatrix.sync.aligned.m8n8.x4.shared.b16 {%0,%1,%2,%3}, [%4];"
                 : "=r"(r[0]), "=r"(r[1]), "=r"(r[2]), "=r"(r[3]) : "r"(addr));
}
__device__ __forceinline__ void mma8(float* c, const uint32_t* a, const uint32_t* b) {
    asm volatile(
        "mma.sync.aligned.m16n8k8.row.col.f32.tf32.tf32.f32 "
        "{%0,%1,%2,%3}, {%4,%5,%6,%7}, {%8,%9}, {%0,%1,%2,%3};"
        : "+f"(c[0]), "+f"(c[1]), "+f"(c[2]), "+f"(c[3])
        : "r"(a[0]), "r"(a[1]), "r"(a[2]), "r"(a[3]), "r"(b[0]), "r"(b[1]));
}

}  // namespace

__global__ __launch_bounds__(256, 2)
void BlockDiagonalGRU_kernel(
    const float* __restrict__ x, const float* __restrict__ h,
    const float* __restrict__ Wih, const float* __restrict__ Whh,
    const float* __restrict__ bih, const float* __restrict__ bhh,
    float* __restrict__ out)
{
    extern __shared__ float smf[];
    const uint32_t smb = smem_u32(smf);

    const int tid  = threadIdx.x;
    const int wid  = tid >> 5;
    const int lane = tid & 31;
    const int gq   = lane >> 2;
    const int t4   = lane & 3;

    const int m  = blockIdx.x & 7;
    const int c  = (blockIdx.x >> 3) & 15;      // 16 col tiles of 32
    const int nb = blockIdx.x >> 7;

    const int wr = (wid >> 1) * 32;   // 4 m-groups of 32 rows
    const int wc = (wid & 1) * 16;    // 2 n-groups of 16 cols

    // ---- fill assignments: 4 A-chunks + 3 W-chunks of 16B per thread ----
    int aoff[4];  uint32_t soffA[4];
    #pragma unroll
    for (int ii = 0; ii < 4; ++ii) {
        const int id = tid + 256 * ii;           // 0..1023
        const int row = id >> 3, q = id & 7;
        aoff[ii]  = row * HID + q * 4;
        soffA[ii] = (uint32_t)(row * STRIDE * 4 + q * 16);
    }
    int woff[3];  uint32_t soffB[3];
    #pragma unroll
    for (int ii = 0; ii < 3; ++ii) {
        const int id = tid + 256 * ii;           // 0..767
        const int wrow = id >> 3, q = id & 7;    // wrow = gate*32 + n_local
        const int gate = wrow >> 5, nl = wrow & 31;
        woff[ii]  = (gate * BS + c * 32 + nl) * BS + q * 4;
        soffB[ii] = (uint32_t)(A_FB + wrow * STRIDE * 4 + q * 16);
    }

    const float* Abase[2] = { x + (size_t)(m * 128) * HID + nb * BS,
                              h + (size_t)(m * 128) * HID + nb * BS };
    const float* Wbase[2] = { Wih + (size_t)nb * G3 * BS,
                              Whh + (size_t)nb * G3 * BS };

    // per-lane ldmatrix byte offsets (layout validated in R3/R4)
    const uint32_t laneA =
        (uint32_t)(((((lane >> 3) & 1) * 8 + (lane & 7)) * STRIDE + (lane >> 4) * 4) * 4);
    const uint32_t laneB =
        (uint32_t)((((lane >> 4) * 8 + (lane & 7)) * STRIDE + ((lane >> 3) & 1) * 4) * 4)
        + (uint32_t)A_FB;

    float accR[2][2][4] = {}, accZ[2][2][4] = {};
    float accI[2][2][4] = {}, accH[2][2][4] = {};

    auto fill = [&](int st, int it) {
        const int p  = it >> 4;
        const int kc = (it & 15) * 32;
        const uint32_t sb0 = smb + (uint32_t)(st * STAGE_B);
        const float* Ab = Abase[p] + kc;
        #pragma unroll
        for (int ii = 0; ii < 4; ++ii) cp16(sb0 + soffA[ii], Ab + aoff[ii]);
        const float* Wb = Wbase[p] + kc;
        #pragma unroll
        for (int ii = 0; ii < 3; ++ii) cp16(sb0 + soffB[ii], Wb + woff[ii]);
        asm volatile("cp.async.commit_group;" ::: "memory");
    };

    fill(0, 0); fill(1, 1);

    int st = 0;                                  // stage of chunk i (mod 3)
    for (int i = 0; i < 32; ++i) {
        if (i <= 30) asm volatile("cp.async.wait_group 1;" ::: "memory");
        else         asm volatile("cp.async.wait_group 0;" ::: "memory");
        __syncthreads();

        const int st2 = (st + 2 >= 3) ? st - 1 : st + 2;   // (st+2)%3
        if (i < 30) fill(st2, i + 2);

        const uint32_t sA = smb + (uint32_t)(st * STAGE_B);
        float (*accN)[2][4] = (i >> 4) ? accH : accI;

        #pragma unroll
        for (int ks = 0; ks < 4; ++ks) {
            uint32_t a[2][4];
            #pragma unroll
            for (int mf = 0; mf < 2; ++mf) {
                ldsm4(a[mf], sA + laneA +
                      (uint32_t)(((wr + mf * 16) * STRIDE + ks * 8) * 4));
                #pragma unroll
                for (int j = 0; j < 4; ++j) a[mf][j] = f2tf32(a[mf][j]);
            }
            #pragma unroll
            for (int g = 0; g < 3; ++g) {
                uint32_t b4[4];
                ldsm4(b4, sA + laneB +
                      (uint32_t)(((wc + g * 32) * STRIDE + ks * 8) * 4));
                #pragma unroll
                for (int n2 = 0; n2 < 2; ++n2) {
                    if (g == 0) {
                        mma8(accR[0][n2], a[0], b4 + n2 * 2);
                        mma8(accR[1][n2], a[1], b4 + n2 * 2);
                    } else if (g == 1) {
                        mma8(accZ[0][n2], a[0], b4 + n2 * 2);
                        mma8(accZ[1][n2], a[1], b4 + n2 * 2);
                    } else {
                        mma8(accN[0][n2], a[0], b4 + n2 * 2);
                        mma8(accN[1][n2], a[1], b4 + n2 * 2);
                    }
                }
            }
        }
        st = (st + 1 >= 3) ? 0 : st + 1;
    }

    // ---- fused GRU epilogue ----
    const float* bi = bih + nb * G3;
    const float* bh = bhh + nb * G3;

    #pragma unroll
    for (int mf = 0; mf < 2; ++mf) {
        #pragma unroll
        for (int nf = 0; nf < 2; ++nf) {
            const int colb = c * 32 + wc + nf * 8 + 2 * t4;   // col in 512 block
            const int rowb = m * 128 + wr + mf * 16 + gq;
            #pragma unroll
            for (int half = 0; half < 2; ++half) {
                const int row = rowb + 8 * half;
                const int i0  = 2 * half;
                const size_t goff = (size_t)row * HID + nb * BS + colb;
                const float2 hv = *reinterpret_cast<const float2*>(h + goff);
                float res[2];
                #pragma unroll
                for (int k = 0; k < 2; ++k) {
                    const int cb = colb + k;
                    const float rp = accR[mf][nf][i0 + k] * COMP
                                   + __ldg(bi + cb) + __ldg(bh + cb);
                    const float zp = accZ[mf][nf][i0 + k] * COMP
                                   + __ldg(bi + BS + cb) + __ldg(bh + BS + cb);
                    const float ip = accI[mf][nf][i0 + k] * COMP + __ldg(bi + 2 * BS + cb);
                    const float hp = accH[mf][nf][i0 + k] * COMP + __ldg(bh + 2 * BS + cb);
                    const float r  = sig_ap(rp);
                    const float z  = sig_ap(zp);
                    const float ng = tanh_ap(fmaf(r, hp, ip));
                    const float hval = (k == 0) ? hv.x : hv.y;
                    res[k] = fmaf(z, hval - ng, ng);
                }
                *reinterpret_cast<float2*>(out + goff) = make_float2(res[0], res[1]);
            }
        }
    }
}

extern "C" void kernel_launch(void* const* d_in, const int* in_sizes, int n_in,
                              void* d_out, int out_size) {
    (void)in_sizes; (void)n_in; (void)out_size;
    cudaFuncSetAttribute(BlockDiagonalGRU_kernel,
                         cudaFuncAttributeMaxDynamicSharedMemorySize, SMEM_BYTES);
    BlockDiagonalGRU_kernel<<<1024, 256, SMEM_BYTES>>>(
        (const float*)d_in[0], (const float*)d_in[1],
        (const float*)d_in[2], (const float*)d_in[3],
        (const float*)d_in[4], (const float*)d_in[5],
        (float*)d_out);
}

// round 6
// speedup vs baseline: 1.2572x; 1.0453x over previous
#include <cuda_runtime.h>
#include <cuda_bf16.h>
#include <cstdint>

// ---------------------------------------------------------------------------
// BlockDiagonalGRU via mma.sync tf32 + cp.async + ldmatrix (sm_100 base).
// R6: no A-side cvt (HW tf32 truncation, bias-compensated) + ks-level
//     fragment double-buffering to kill intra-warp ldsm->mma bubbles.
//   Grid: 1024 CTAs = nb(8) x ctile(16 x 32 cols) x mtile(8 x 128 rows).
//   CTA tile 128x32 per gate; 256 thr, 8 warps as 4(m) x 2(n), warp 32x16.
//   2 CTAs/SM. Accs: R (fused), Z (fused), IN, HN -> 64 f32/thread.
//   3-stage cp.async ring, TK=32. Both A and W fed as raw fp32 (HW RZ
//   truncation); epilogue multiplies by (1+2^-11)^2 ~= 1+2^-10.
// ---------------------------------------------------------------------------

namespace {

constexpr int HID = 4096;
constexpr int BS  = 512;
constexpr int G3  = 1536;

constexpr int STRIDE = 36;                      // words per 32-k row (+4 pad)
constexpr int A_ROWS = 128;
constexpr int B_ROWS = 96;                      // 3 gates x 32
constexpr int A_FB    = A_ROWS * STRIDE * 4;    // 18432 B
constexpr int STAGE_B = (A_ROWS + B_ROWS) * STRIDE * 4;  // 32256 B
constexpr int STAGES  = 3;
constexpr int SMEM_BYTES = STAGES * STAGE_B;    // 96768 B

constexpr float COMP = 1.0009765625f;           // (1+2^-11)^2 ~= 1+2^-10

__device__ __forceinline__ uint32_t smem_u32(const void* p) {
    uint32_t a;
    asm("{ .reg .u64 t; cvta.to.shared.u64 t, %1; cvt.u32.u64 %0, t; }"
        : "=r"(a) : "l"(p));
    return a;
}
__device__ __forceinline__ float tanh_ap(float x) {
    float y;
    asm("tanh.approx.f32 %0, %1;" : "=f"(y) : "f"(x));
    return y;
}
__device__ __forceinline__ float sig_ap(float x) {
    return fmaf(0.5f, tanh_ap(0.5f * x), 0.5f);
}
__device__ __forceinline__ void cp16(uint32_t dst, const void* src) {
    asm volatile("cp.async.cg.shared.global [%0], [%1], 16;"
                 :: "r"(dst), "l"(src) : "memory");
}
__device__ __forceinline__ void ldsm4(uint32_t* r, uint32_t addr) {
    asm volatile("ldmatrix.sync.aligned.m8n8.x4.shared.b16 {%0,%1,%2,%3}, [%4];"
                 : "=r"(r[0]), "=r"(r[1]), "=r"(r[2]), "=r"(r[3]) : "r"(addr));
}
__device__ __forceinline__ void mma8(float* c, const uint32_t* a, const uint32_t* b) {
    asm volatile(
        "mma.sync.aligned.m16n8k8.row.col.f32.tf32.tf32.f32 "
        "{%0,%1,%2,%3}, {%4,%5,%6,%7}, {%8,%9}, {%0,%1,%2,%3};"
        : "+f"(c[0]), "+f"(c[1]), "+f"(c[2]), "+f"(c[3])
        : "r"(a[0]), "r"(a[1]), "r"(a[2]), "r"(a[3]), "r"(b[0]), "r"(b[1]));
}

}  // namespace

__global__ __launch_bounds__(256, 2)
void BlockDiagonalGRU_kernel(
    const float* __restrict__ x, const float* __restrict__ h,
    const float* __restrict__ Wih, const float* __restrict__ Whh,
    const float* __restrict__ bih, const float* __restrict__ bhh,
    float* __restrict__ out)
{
    extern __shared__ float smf[];
    const uint32_t smb = smem_u32(smf);

    const int tid  = threadIdx.x;
    const int wid  = tid >> 5;
    const int lane = tid & 31;
    const int gq   = lane >> 2;
    const int t4   = lane & 3;

    const int m  = blockIdx.x & 7;
    const int c  = (blockIdx.x >> 3) & 15;      // 16 col tiles of 32
    const int nb = blockIdx.x >> 7;

    const int wr = (wid >> 1) * 32;   // 4 m-groups of 32 rows
    const int wc = (wid & 1) * 16;    // 2 n-groups of 16 cols

    // ---- fill assignments: 4 A-chunks + 3 W-chunks of 16B per thread ----
    int aoff[4];  uint32_t soffA[4];
    #pragma unroll
    for (int ii = 0; ii < 4; ++ii) {
        const int id = tid + 256 * ii;           // 0..1023
        const int row = id >> 3, q = id & 7;
        aoff[ii]  = row * HID + q * 4;
        soffA[ii] = (uint32_t)(row * STRIDE * 4 + q * 16);
    }
    int woff[3];  uint32_t soffB[3];
    #pragma unroll
    for (int ii = 0; ii < 3; ++ii) {
        const int id = tid + 256 * ii;           // 0..767
        const int wrow = id >> 3, q = id & 7;    // wrow = gate*32 + n_local
        const int gate = wrow >> 5, nl = wrow & 31;
        woff[ii]  = (gate * BS + c * 32 + nl) * BS + q * 4;
        soffB[ii] = (uint32_t)(A_FB + wrow * STRIDE * 4 + q * 16);
    }

    const float* Abase[2] = { x + (size_t)(m * 128) * HID + nb * BS,
                              h + (size_t)(m * 128) * HID + nb * BS };
    const float* Wbase[2] = { Wih + (size_t)nb * G3 * BS,
                              Whh + (size_t)nb * G3 * BS };

    // per-lane ldmatrix byte offsets (layout validated R3-R5)
    const uint32_t laneA =
        (uint32_t)(((((lane >> 3) & 1) * 8 + (lane & 7)) * STRIDE + (lane >> 4) * 4) * 4)
        + (uint32_t)(wr * STRIDE * 4);
    const uint32_t laneB =
        (uint32_t)((((lane >> 4) * 8 + (lane & 7)) * STRIDE + ((lane >> 3) & 1) * 4) * 4)
        + (uint32_t)A_FB + (uint32_t)(wc * STRIDE * 4);

    float accR[2][2][4] = {}, accZ[2][2][4] = {};
    float accI[2][2][4] = {}, accH[2][2][4] = {};

    auto fill = [&](int st, int it) {
        const int p  = it >> 4;
        const int kc = (it & 15) * 32;
        const uint32_t sb0 = smb + (uint32_t)(st * STAGE_B);
        const float* Ab = Abase[p] + kc;
        #pragma unroll
        for (int ii = 0; ii < 4; ++ii) cp16(sb0 + soffA[ii], Ab + aoff[ii]);
        const float* Wb = Wbase[p] + kc;
        #pragma unroll
        for (int ii = 0; ii < 3; ++ii) cp16(sb0 + soffB[ii], Wb + woff[ii]);
        asm volatile("cp.async.commit_group;" ::: "memory");
    };

    fill(0, 0); fill(1, 1);

    // fragment double buffers: [buf][frag][4]
    uint32_t fa[2][2][4];   // A: mf = 0,1  (rows wr+0, wr+16)
    uint32_t fb[2][3][4];   // B: g  = 0,1,2

    int st = 0;
    for (int i = 0; i < 32; ++i) {
        if (i <= 30) asm volatile("cp.async.wait_group 1;" ::: "memory");
        else         asm volatile("cp.async.wait_group 0;" ::: "memory");
        __syncthreads();

        const uint32_t sA = smb + (uint32_t)(st * STAGE_B);
        const uint32_t aA = sA + laneA;
        const uint32_t aB = sA + laneB;

        // prime buffer 0 with ks=0 fragments (before issuing fills)
        ldsm4(fa[0][0], aA + 0u);
        ldsm4(fa[0][1], aA + (uint32_t)(16 * STRIDE * 4));
        ldsm4(fb[0][0], aB + 0u);
        ldsm4(fb[0][1], aB + (uint32_t)(32 * STRIDE * 4));
        ldsm4(fb[0][2], aB + (uint32_t)(64 * STRIDE * 4));

        const int st2 = (st + 2 >= 3) ? st - 1 : st + 2;   // (st+2)%3
        if (i < 30) fill(st2, i + 2);

        float (*accN)[2][4] = (i >> 4) ? accH : accI;

        #pragma unroll
        for (int ks = 0; ks < 4; ++ks) {
            const int cur = ks & 1;
            if (ks < 3) {
                const int nxt = cur ^ 1;
                const uint32_t ko = (uint32_t)((ks + 1) * 32);  // 8 words * 4B
                ldsm4(fa[nxt][0], aA + ko);
                ldsm4(fa[nxt][1], aA + ko + (uint32_t)(16 * STRIDE * 4));
                ldsm4(fb[nxt][0], aB + ko);
                ldsm4(fb[nxt][1], aB + ko + (uint32_t)(32 * STRIDE * 4));
                ldsm4(fb[nxt][2], aB + ko + (uint32_t)(64 * STRIDE * 4));
            }
            #pragma unroll
            for (int n2 = 0; n2 < 2; ++n2) {
                mma8(accR[0][n2], fa[cur][0], fb[cur][0] + n2 * 2);
                mma8(accR[1][n2], fa[cur][1], fb[cur][0] + n2 * 2);
                mma8(accZ[0][n2], fa[cur][0], fb[cur][1] + n2 * 2);
                mma8(accZ[1][n2], fa[cur][1], fb[cur][1] + n2 * 2);
                mma8(accN[0][n2], fa[cur][0], fb[cur][2] + n2 * 2);
                mma8(accN[1][n2], fa[cur][1], fb[cur][2] + n2 * 2);
            }
        }
        st = (st + 1 >= 3) ? 0 : st + 1;
    }

    // ---- fused GRU epilogue ----
    const float* bi = bih + nb * G3;
    const float* bh = bhh + nb * G3;

    #pragma unroll
    for (int mf = 0; mf < 2; ++mf) {
        #pragma unroll
        for (int nf = 0; nf < 2; ++nf) {
            const int colb = c * 32 + wc + nf * 8 + 2 * t4;   // col in 512 block
            const int rowb = m * 128 + wr + mf * 16 + gq;
            #pragma unroll
            for (int half = 0; half < 2; ++half) {
                const int row = rowb + 8 * half;
                const int i0  = 2 * half;
                const size_t goff = (size_t)row * HID + nb * BS + colb;
                const float2 hv = *reinterpret_cast<const float2*>(h + goff);
                float res[2];
                #pragma unroll
                for (int k = 0; k < 2; ++k) {
                    const int cb = colb + k;
                    const float rp = accR[mf][nf][i0 + k] * COMP
                                   + __ldg(bi + cb) + __ldg(bh + cb);
                    const float zp = accZ[mf][nf][i0 + k] * COMP
                                   + __ldg(bi + BS + cb) + __ldg(bh + BS + cb);
                    const float ip = accI[mf][nf][i0 + k] * COMP + __ldg(bi + 2 * BS + cb);
                    const float hp = accH[mf][nf][i0 + k] * COMP + __ldg(bh + 2 * BS + cb);
                    const float r  = sig_ap(rp);
                    const float z  = sig_ap(zp);
                    const float ng = tanh_ap(fmaf(r, hp, ip));
                    const float hval = (k == 0) ? hv.x : hv.y;
                    res[k] = fmaf(z, hval - ng, ng);
                }
                *reinterpret_cast<float2*>(out + goff) = make_float2(res[0], res[1]);
            }
        }
    }
}

extern "C" void kernel_launch(void* const* d_in, const int* in_sizes, int n_in,
                              void* d_out, int out_size) {
    (void)in_sizes; (void)n_in; (void)out_size;
    cudaFuncSetAttribute(BlockDiagonalGRU_kernel,
                         cudaFuncAttributeMaxDynamicSharedMemorySize, SMEM_BYTES);
    BlockDiagonalGRU_kernel<<<1024, 256, SMEM_BYTES>>>(
        (const float*)d_in[0], (const float*)d_in[1],
        (const float*)d_in[2], (const float*)d_in[3],
        (const float*)d_in[4], (const float*)d_in[5],
        (float*)d_out);
}